// round 14
// baseline (speedup 1.0000x reference)
#include <cuda_runtime.h>
#include <cuda_bf16.h>
#include <cstdint>

#define B 1024
#define DIM 32
#define DIMH 1024
#define DIMC 512

typedef __nv_bfloat16 bf16;
typedef __nv_bfloat162 bf162;

// ------------------------- device scratch -------------------------
__device__ float g_swout[DIMH];
__device__ bf16 g_Wz0t_h[DIM * DIMH];
__device__ float g_Wx1t[DIM * DIMH];
__device__ float g_Wx2t[DIM * DIMH];

__device__ bf16 g_SW1hi[DIMH * DIMH], g_SW1lo[DIMH * DIMH];
__device__ bf16 g_SW2hi[DIMH * DIMH], g_SW2lo[DIMH * DIMH];
__device__ bf16 g_SW1thi[DIMH * DIMH], g_SW1tlo[DIMH * DIMH];
__device__ bf16 g_SW2thi[DIMH * DIMH], g_SW2tlo[DIMH * DIMH];
__device__ bf16 g_Wc0hi[DIMH * DIMC], g_Wc0lo[DIMH * DIMC];
__device__ bf16 g_Wc1hi[DIMH * DIMC], g_Wc1lo[DIMH * DIMC];
__device__ bf16 g_Wc2hi[DIMH * DIMC], g_Wc2lo[DIMH * DIMC];
__device__ bf16 g_Wz0hi[DIMH * DIM], g_Wz0lo[DIMH * DIM];
__device__ bf16 g_Wx1hi[DIMH * DIM], g_Wx1lo[DIMH * DIM];
__device__ bf16 g_Wx2hi[DIMH * DIM], g_Wx2lo[DIMH * DIM];

__device__ bf16 g_xhi[B * DIM], g_xlo[B * DIM];
__device__ bf16 g_chi[B * DIMC], g_clo[B * DIMC];
__device__ bf16 g_z0hi[B * DIMH], g_z0lo[B * DIMH];
__device__ bf16 g_z1hi[B * DIMH], g_z1lo[B * DIMH];
__device__ bf16 g_G2hi[B * DIMH], g_G2lo[B * DIMH];
__device__ bf16 g_G1hi[B * DIMH], g_G1lo[B * DIMH];

__device__ float g_D0[B * DIMH], g_E0[B * DIMH];
__device__ float g_D1[B * DIMH], g_E1[B * DIMH];
__device__ bf16 g_D0h[B * DIMH], g_D1h[B * DIMH];
__device__ float g_G2[B * DIMH], g_V2[B * DIMH];
__device__ float g_G1[B * DIMH], g_V1[B * DIMH];
__device__ float g_G0[B * DIMH], g_V0[B * DIMH];

__device__ bf16 g_M1t[(size_t)B * DIM * DIMH];
__device__ bf16 g_M2t[(size_t)B * DIM * DIMH];

// ------------------------- math helpers -------------------------
__device__ __forceinline__ float softplusf(float x) {
    return x > 20.f ? x : log1pf(expf(x));
}
__device__ __forceinline__ float gspf(float x) {
    const float SHP = 1.2533141373155003f;
    float ex = expf(-0.5f * x * x);
    float er = erff(x * 0.7071067811865475f);
    return (SHP * x * er + ex + SHP * x) * (1.0f / (2.0f * SHP));
}
__device__ __forceinline__ float ncdf(float x) {
    return 0.5f * (1.f + erff(x * 0.7071067811865475f));
}
__device__ __forceinline__ float npdf(float x) {
    return 0.3989422804014327f * expf(-0.5f * x * x);
}
__device__ __forceinline__ void bsplit(float v, bf16& h, bf16& l) {
    h = __float2bfloat16(v);
    l = __float2bfloat16(v - __bfloat162float(h));
}
__device__ __forceinline__ uint32_t smemu32(const void* p) {
    uint32_t a;
    asm("{ .reg .u64 t; cvta.to.shared.u64 t, %1; cvt.u32.u64 %0, t; }" : "=r"(a) : "l"(p));
    return a;
}

#define LDSM4(F, ADDR) asm volatile( \
    "ldmatrix.sync.aligned.m8n8.x4.shared.b16 {%0,%1,%2,%3}, [%4];" \
    : "=r"((F)[0]), "=r"((F)[1]), "=r"((F)[2]), "=r"((F)[3]) : "r"(ADDR))
#define LDSM2(F, ADDR) asm volatile( \
    "ldmatrix.sync.aligned.m8n8.x2.shared.b16 {%0,%1}, [%2];" \
    : "=r"((F)[0]), "=r"((F)[1]) : "r"(ADDR))
#define MMA_BF16(ACC, AF, BF) asm volatile( \
    "mma.sync.aligned.m16n8k16.row.col.f32.bf16.bf16.f32 " \
    "{%0,%1,%2,%3}, {%4,%5,%6,%7}, {%8,%9}, {%0,%1,%2,%3};" \
    : "+f"((ACC)[0]), "+f"((ACC)[1]), "+f"((ACC)[2]), "+f"((ACC)[3]) \
    : "r"((AF)[0]), "r"((AF)[1]), "r"((AF)[2]), "r"((AF)[3]), \
      "r"((BF)[0]), "r"((BF)[1]))

// ------------------------- prep -------------------------
__global__ void k_prep(const float* __restrict__ Wz1, const float* __restrict__ Wz2,
                       const float* __restrict__ Wzout,
                       const float* __restrict__ Wz0, const float* __restrict__ Wx1,
                       const float* __restrict__ Wx2) {
    int n = DIMH * DIMH;
    for (int i = blockIdx.x * blockDim.x + threadIdx.x; i < n; i += gridDim.x * blockDim.x) {
        float s1 = softplusf(Wz1[i]) * (1.f / DIMH);
        float s2 = softplusf(Wz2[i]) * (1.f / DIMH);
        bsplit(s1, g_SW1hi[i], g_SW1lo[i]);
        bsplit(s2, g_SW2hi[i], g_SW2lo[i]);
        if (i < DIMH) g_swout[i] = softplusf(Wzout[i]) * (1.f / DIMH);
        if (i < DIM * DIMH) {
            int k = i >> 5, j = i & 31;
            g_Wz0t_h[j * DIMH + k] = __float2bfloat16(Wz0[i]);
            g_Wx1t[j * DIMH + k] = Wx1[i];
            g_Wx2t[j * DIMH + k] = Wx2[i];
            bsplit(Wz0[i], g_Wz0hi[i], g_Wz0lo[i]);
            bsplit(Wx1[i], g_Wx1hi[i], g_Wx1lo[i]);
            bsplit(Wx2[i], g_Wx2hi[i], g_Wx2lo[i]);
        }
    }
}

__global__ void k_split(const float* __restrict__ cv, const float* __restrict__ xv,
                        const float* __restrict__ Wc0, const float* __restrict__ Wc1,
                        const float* __restrict__ Wc2) {
    int n = DIMH * DIMC;
    for (int i = blockIdx.x * blockDim.x + threadIdx.x; i < n; i += gridDim.x * blockDim.x) {
        bsplit(cv[i], g_chi[i], g_clo[i]);
        bsplit(Wc0[i], g_Wc0hi[i], g_Wc0lo[i]);
        bsplit(Wc1[i], g_Wc1hi[i], g_Wc1lo[i]);
        bsplit(Wc2[i], g_Wc2hi[i], g_Wc2lo[i]);
        if (i < B * DIM) bsplit(xv[i], g_xhi[i], g_xlo[i]);
    }
}

__global__ void k_tr() {
    __shared__ bf16 t[32][33];
    const bf16* src; bf16* dst;
    switch (blockIdx.z) {
        case 0: src = g_SW1hi; dst = g_SW1thi; break;
        case 1: src = g_SW1lo; dst = g_SW1tlo; break;
        case 2: src = g_SW2hi; dst = g_SW2thi; break;
        default: src = g_SW2lo; dst = g_SW2tlo; break;
    }
    int jx = blockIdx.x * 32, ky = blockIdx.y * 32;
    int tx = threadIdx.x, ty = threadIdx.y;
#pragma unroll
    for (int r = 0; r < 4; r++)
        t[ty + 8 * r][tx] = src[(ky + ty + 8 * r) * DIMH + jx + tx];
    __syncthreads();
#pragma unroll
    for (int r = 0; r < 4; r++)
        dst[(jx + ty + 8 * r) * DIMH + ky + tx] = t[tx][ty + 8 * r];
}

// ------------------------- split-bf16 forward layer (A-tile 64, B-tile 128) ----------
// 8 warps as 2m x 4n; acc[2][4][4]; 2 CTAs/SM.
__global__ __launch_bounds__(256, 2) void k_fwd_tc(
    const bf16* __restrict__ A1hi, const bf16* __restrict__ A1lo,
    const bf16* __restrict__ B1hi, const bf16* __restrict__ B1lo, int K1,
    const bf16* __restrict__ A2hi, const bf16* __restrict__ A2lo,
    const bf16* __restrict__ B2hi, const bf16* __restrict__ B2lo, int K2,
    const bf16* __restrict__ A3hi, const bf16* __restrict__ A3lo,
    const bf16* __restrict__ B3hi, const bf16* __restrict__ B3lo, int K3,
    const float* __restrict__ bias1, const float* __restrict__ bias2,
    const float* __restrict__ bias3,
    const float* __restrict__ an_b, const float* __restrict__ an_logs,
    const float* __restrict__ swout,
    bf16* __restrict__ zhi, bf16* __restrict__ zlo,
    float* __restrict__ outD, float* __restrict__ outE, bf16* __restrict__ outDh,
    float* __restrict__ outG, bf16* __restrict__ ghi, bf16* __restrict__ glo,
    float* __restrict__ outV)
{
    __shared__ __align__(16) bf16 Ah_s[64 * 40], Al_s[64 * 40];
    __shared__ __align__(16) bf16 Bh_s[128 * 40], Bl_s[128 * 40];
    int k0 = blockIdx.x * 128, b0 = blockIdx.y * 64;
    int tid = threadIdx.x, lane = tid & 31, w = tid >> 5;
    int wm = w >> 2, wn = w & 3;
    int pm = tid >> 1, pk = (tid & 1) * 16;
    bool aStage = tid < 128;

    int n1 = K1 >> 5, n2 = K2 >> 5, n3 = K3 >> 5;
    int nCh = n1 + n2 + n3;

    uint32_t ahB = smemu32(Ah_s), alB = smemu32(Al_s);
    uint32_t bhB = smemu32(Bh_s), blB = smemu32(Bl_s);

    float acc[2][4][4] = {};
    uint4 rA0, rA1, rL0, rL1, rB0, rB1, rM0, rM1;

    auto loadCh = [&](int ch) {
        const bf16 *Ah, *Al, *Bh, *Bl; int K, kt;
        if (ch < n1)            { Ah = A1hi; Al = A1lo; Bh = B1hi; Bl = B1lo; K = K1; kt = ch << 5; }
        else if (ch < n1 + n2)  { Ah = A2hi; Al = A2lo; Bh = B2hi; Bl = B2lo; K = K2; kt = (ch - n1) << 5; }
        else                    { Ah = A3hi; Al = A3lo; Bh = B3hi; Bl = B3lo; K = K3; kt = (ch - n1 - n2) << 5; }
        size_t bo = (size_t)(k0 + pm) * K + kt + pk;
        rB0 = *(const uint4*)(Bh + bo); rB1 = *(const uint4*)(Bh + bo + 8);
        rM0 = *(const uint4*)(Bl + bo); rM1 = *(const uint4*)(Bl + bo + 8);
        if (aStage) {
            size_t ao = (size_t)(b0 + pm) * K + kt + pk;
            rA0 = *(const uint4*)(Ah + ao); rA1 = *(const uint4*)(Ah + ao + 8);
            rL0 = *(const uint4*)(Al + ao); rL1 = *(const uint4*)(Al + ao + 8);
        }
    };

    int aRowL = (lane & 7) + ((lane >> 3) & 1) * 8;
    int aColL = (lane >> 4) * 8;
    int bl_ = lane & 15;
    int bRowL = bl_ & 7, bColL = ((bl_ >> 3) & 1) * 8;

    loadCh(0);
    for (int ch = 0; ch < nCh; ch++) {
        if (aStage) {
            *(uint4*)&Ah_s[pm * 40 + pk] = rA0; *(uint4*)&Ah_s[pm * 40 + pk + 8] = rA1;
            *(uint4*)&Al_s[pm * 40 + pk] = rL0; *(uint4*)&Al_s[pm * 40 + pk + 8] = rL1;
        }
        *(uint4*)&Bh_s[pm * 40 + pk] = rB0; *(uint4*)&Bh_s[pm * 40 + pk + 8] = rB1;
        *(uint4*)&Bl_s[pm * 40 + pk] = rM0; *(uint4*)&Bl_s[pm * 40 + pk + 8] = rM1;
        __syncthreads();
        if (ch + 1 < nCh) loadCh(ch + 1);
#pragma unroll
        for (int kk = 0; kk < 32; kk += 16) {
            uint32_t ah[2][4], al[2][4];
#pragma unroll
            for (int mi = 0; mi < 2; mi++) {
                int row = wm * 32 + mi * 16 + aRowL;
                LDSM4(ah[mi], ahB + (uint32_t)(row * 40 + kk + aColL) * 2);
                LDSM4(al[mi], alB + (uint32_t)(row * 40 + kk + aColL) * 2);
            }
            uint32_t bh[4][2], bl2[4][2];
#pragma unroll
            for (int ni = 0; ni < 4; ni++) {
                int row = wn * 32 + ni * 8 + bRowL;
                LDSM2(bh[ni], bhB + (uint32_t)(row * 40 + kk + bColL) * 2);
                LDSM2(bl2[ni], blB + (uint32_t)(row * 40 + kk + bColL) * 2);
            }
#pragma unroll
            for (int mi = 0; mi < 2; mi++)
#pragma unroll
                for (int ni = 0; ni < 4; ni++) {
                    MMA_BF16(acc[mi][ni], ah[mi], bh[ni]);
                    MMA_BF16(acc[mi][ni], ah[mi], bl2[ni]);
                    MMA_BF16(acc[mi][ni], al[mi], bh[ni]);
                }
        }
        __syncthreads();
    }

    bool gmode = (swout != nullptr);
#pragma unroll
    for (int mi = 0; mi < 2; mi++) {
        int m0 = wm * 32 + mi * 16 + (lane >> 2);
        int bA = b0 + m0, bB = b0 + m0 + 8;
#pragma unroll
        for (int ni = 0; ni < 4; ni++) {
            int k = k0 + wn * 32 + ni * 8 + (lane & 3) * 2;
            float2 bb1 = *(const float2*)(bias1 + k);
            float2 bb2 = *(const float2*)(bias2 + k);
            float2 bb3 = bias3 ? *(const float2*)(bias3 + k) : make_float2(0.f, 0.f);
            float2 ab = *(const float2*)(an_b + k);
            float2 alg = *(const float2*)(an_logs + k);
            float aa0 = expf(alg.x), aa1 = expf(alg.y);
            float h00 = acc[mi][ni][0] + bb1.x + bb2.x + bb3.x;
            float h01 = acc[mi][ni][1] + bb1.y + bb2.y + bb3.y;
            float h10 = acc[mi][ni][2] + bb1.x + bb2.x + bb3.x;
            float h11 = acc[mi][ni][3] + bb1.y + bb2.y + bb3.y;
            float p00 = (h00 + ab.x) * aa0, p01 = (h01 + ab.y) * aa1;
            float p10 = (h10 + ab.x) * aa0, p11 = (h11 + ab.y) * aa1;
            float d00 = aa0 * ncdf(p00), d01 = aa1 * ncdf(p01);
            float d10 = aa0 * ncdf(p10), d11 = aa1 * ncdf(p11);
            float e00 = aa0 * aa0 * npdf(p00), e01 = aa1 * aa1 * npdf(p01);
            float e10 = aa0 * aa0 * npdf(p10), e11 = aa1 * aa1 * npdf(p11);
            if (!gmode) {
                float z00 = gspf(p00), z01 = gspf(p01);
                float z10 = gspf(p10), z11 = gspf(p11);
                bf162 zh, zl;
                bsplit(z00, zh.x, zl.x); bsplit(z01, zh.y, zl.y);
                *(bf162*)&zhi[(size_t)bA * DIMH + k] = zh;
                *(bf162*)&zlo[(size_t)bA * DIMH + k] = zl;
                bsplit(z10, zh.x, zl.x); bsplit(z11, zh.y, zl.y);
                *(bf162*)&zhi[(size_t)bB * DIMH + k] = zh;
                *(bf162*)&zlo[(size_t)bB * DIMH + k] = zl;
                *(float2*)&outD[(size_t)bA * DIMH + k] = make_float2(d00, d01);
                *(float2*)&outD[(size_t)bB * DIMH + k] = make_float2(d10, d11);
                *(float2*)&outE[(size_t)bA * DIMH + k] = make_float2(e00, e01);
                *(float2*)&outE[(size_t)bB * DIMH + k] = make_float2(e10, e11);
                *(bf162*)&outDh[(size_t)bA * DIMH + k] = __floats2bfloat162_rn(d00, d01);
                *(bf162*)&outDh[(size_t)bB * DIMH + k] = __floats2bfloat162_rn(d10, d11);
            } else {
                float2 so = *(const float2*)(swout + k);
                float g00 = so.x * d00, g01 = so.y * d01;
                float g10 = so.x * d10, g11 = so.y * d11;
                *(float2*)&outG[(size_t)bA * DIMH + k] = make_float2(g00, g01);
                *(float2*)&outG[(size_t)bB * DIMH + k] = make_float2(g10, g11);
                *(float2*)&outV[(size_t)bA * DIMH + k] = make_float2(so.x * e00, so.y * e01);
                *(float2*)&outV[(size_t)bB * DIMH + k] = make_float2(so.x * e10, so.y * e11);
                bf162 gh, gl;
                bsplit(g00, gh.x, gl.x); bsplit(g01, gh.y, gl.y);
                *(bf162*)&ghi[(size_t)bA * DIMH + k] = gh;
                *(bf162*)&glo[(size_t)bA * DIMH + k] = gl;
                bsplit(g10, gh.x, gl.x); bsplit(g11, gh.y, gl.y);
                *(bf162*)&ghi[(size_t)bB * DIMH + k] = gh;
                *(bf162*)&glo[(size_t)bB * DIMH + k] = gl;
            }
        }
    }
}

// ------------------------- split-bf16 backward u (A-tile 64, B-tile 128) -------------
__global__ __launch_bounds__(256, 2) void k_u_tc(
    const bf16* __restrict__ Ghi, const bf16* __restrict__ Glo,
    const bf16* __restrict__ SWthi, const bf16* __restrict__ SWtlo,
    const float* __restrict__ dvec, const float* __restrict__ evec,
    float* __restrict__ outG, bf16* __restrict__ ghi, bf16* __restrict__ glo,
    float* __restrict__ outV)
{
    __shared__ __align__(16) bf16 Ah_s[64 * 40], Al_s[64 * 40];
    __shared__ __align__(16) bf16 Bh_s[128 * 40], Bl_s[128 * 40];
    int j0 = blockIdx.x * 128, b0 = blockIdx.y * 64;
    int tid = threadIdx.x, lane = tid & 31, w = tid >> 5;
    int wm = w >> 2, wn = w & 3;
    int pm = tid >> 1, pk = (tid & 1) * 16;
    bool aStage = tid < 128;

    uint32_t ahB = smemu32(Ah_s), alB = smemu32(Al_s);
    uint32_t bhB = smemu32(Bh_s), blB = smemu32(Bl_s);

    const bf16* aH = Ghi + (size_t)(b0 + pm) * DIMH;
    const bf16* aL = Glo + (size_t)(b0 + pm) * DIMH;
    const bf16* bH = SWthi + (size_t)(j0 + pm) * DIMH;
    const bf16* bL = SWtlo + (size_t)(j0 + pm) * DIMH;

    float acc[2][4][4] = {};
    uint4 rA0, rA1, rL0, rL1, rB0, rB1, rM0, rM1;
    rB0 = *(const uint4*)(bH + pk); rB1 = *(const uint4*)(bH + pk + 8);
    rM0 = *(const uint4*)(bL + pk); rM1 = *(const uint4*)(bL + pk + 8);
    if (aStage) {
        rA0 = *(const uint4*)(aH + pk); rA1 = *(const uint4*)(aH + pk + 8);
        rL0 = *(const uint4*)(aL + pk); rL1 = *(const uint4*)(aL + pk + 8);
    }

    int aRowL = (lane & 7) + ((lane >> 3) & 1) * 8;
    int aColL = (lane >> 4) * 8;
    int bl_ = lane & 15;
    int bRowL = bl_ & 7, bColL = ((bl_ >> 3) & 1) * 8;

    for (int ch = 0; ch < DIMH / 32; ch++) {
        if (aStage) {
            *(uint4*)&Ah_s[pm * 40 + pk] = rA0; *(uint4*)&Ah_s[pm * 40 + pk + 8] = rA1;
            *(uint4*)&Al_s[pm * 40 + pk] = rL0; *(uint4*)&Al_s[pm * 40 + pk + 8] = rL1;
        }
        *(uint4*)&Bh_s[pm * 40 + pk] = rB0; *(uint4*)&Bh_s[pm * 40 + pk + 8] = rB1;
        *(uint4*)&Bl_s[pm * 40 + pk] = rM0; *(uint4*)&Bl_s[pm * 40 + pk + 8] = rM1;
        __syncthreads();
        if (ch + 1 < DIMH / 32) {
            int kt = (ch + 1) * 32;
            rB0 = *(const uint4*)(bH + kt + pk); rB1 = *(const uint4*)(bH + kt + pk + 8);
            rM0 = *(const uint4*)(bL + kt + pk); rM1 = *(const uint4*)(bL + kt + pk + 8);
            if (aStage) {
                rA0 = *(const uint4*)(aH + kt + pk); rA1 = *(const uint4*)(aH + kt + pk + 8);
                rL0 = *(const uint4*)(aL + kt + pk); rL1 = *(const uint4*)(aL + kt + pk + 8);
            }
        }
#pragma unroll
        for (int kk = 0; kk < 32; kk += 16) {
            uint32_t ah[2][4], al[2][4];
#pragma unroll
            for (int mi = 0; mi < 2; mi++) {
                int row = wm * 32 + mi * 16 + aRowL;
                LDSM4(ah[mi], ahB + (uint32_t)(row * 40 + kk + aColL) * 2);
                LDSM4(al[mi], alB + (uint32_t)(row * 40 + kk + aColL) * 2);
            }
            uint32_t bh[4][2], bl2[4][2];
#pragma unroll
            for (int ni = 0; ni < 4; ni++) {
                int row = wn * 32 + ni * 8 + bRowL;
                LDSM2(bh[ni], bhB + (uint32_t)(row * 40 + kk + bColL) * 2);
                LDSM2(bl2[ni], blB + (uint32_t)(row * 40 + kk + bColL) * 2);
            }
#pragma unroll
            for (int mi = 0; mi < 2; mi++)
#pragma unroll
                for (int ni = 0; ni < 4; ni++) {
                    MMA_BF16(acc[mi][ni], ah[mi], bh[ni]);
                    MMA_BF16(acc[mi][ni], ah[mi], bl2[ni]);
                    MMA_BF16(acc[mi][ni], al[mi], bh[ni]);
                }
        }
        __syncthreads();
    }

#pragma unroll
    for (int mi = 0; mi < 2; mi++) {
        int m0 = wm * 32 + mi * 16 + (lane >> 2);
        int bA = b0 + m0, bB = b0 + m0 + 8;
#pragma unroll
        for (int ni = 0; ni < 4; ni++) {
            int j = j0 + wn * 32 + ni * 8 + (lane & 3) * 2;
            float2 dA = *(const float2*)&dvec[(size_t)bA * DIMH + j];
            float2 dB = *(const float2*)&dvec[(size_t)bB * DIMH + j];
            float2 eA = *(const float2*)&evec[(size_t)bA * DIMH + j];
            float2 eB = *(const float2*)&evec[(size_t)bB * DIMH + j];
            float u00 = acc[mi][ni][0], u01 = acc[mi][ni][1];
            float u10 = acc[mi][ni][2], u11 = acc[mi][ni][3];
            float g00 = u00 * dA.x, g01 = u01 * dA.y;
            float g10 = u10 * dB.x, g11 = u11 * dB.y;
            *(float2*)&outG[(size_t)bA * DIMH + j] = make_float2(g00, g01);
            *(float2*)&outG[(size_t)bB * DIMH + j] = make_float2(g10, g11);
            *(float2*)&outV[(size_t)bA * DIMH + j] =
                make_float2(fmaxf(u00 * eA.x, 0.f), fmaxf(u01 * eA.y, 0.f));
            *(float2*)&outV[(size_t)bB * DIMH + j] =
                make_float2(fmaxf(u10 * eB.x, 0.f), fmaxf(u11 * eB.y, 0.f));
            if (ghi) {
                bf162 gh, gl;
                bsplit(g00, gh.x, gl.x); bsplit(g01, gh.y, gl.y);
                *(bf162*)&ghi[(size_t)bA * DIMH + j] = gh;
                *(bf162*)&glo[(size_t)bA * DIMH + j] = gl;
                bsplit(g10, gh.x, gl.x); bsplit(g11, gh.y, gl.y);
                *(bf162*)&ghi[(size_t)bB * DIMH + j] = gh;
                *(bf162*)&glo[(size_t)bB * DIMH + j] = gl;
            }
        }
    }
}

// ------------------------- f output (SIMT, fp32) -------------------------
__global__ __launch_bounds__(256) void k_f(
    const float* __restrict__ xv,
    const float* __restrict__ Wz0, const float* __restrict__ Wx1,
    const float* __restrict__ Wx2, const float* __restrict__ Wxout,
    const float* __restrict__ w0p, const float* __restrict__ w1p,
    float* __restrict__ out)
{
    __shared__ float Gs[32][65];
    __shared__ float Ws[32][33];
    int b0 = blockIdx.x * 64;
    int tid = threadIdx.x;
    int j = tid & 31;
    int br = (tid >> 5) * 8;
    float acc[8] = {};

    for (int seg = 0; seg < 3; seg++) {
        const float* G = seg == 0 ? g_G0 : (seg == 1 ? g_G1 : g_G2);
        const float* W = seg == 0 ? Wz0  : (seg == 1 ? Wx1  : Wx2);
        for (int kt = 0; kt < DIMH; kt += 32) {
            int lkk = tid & 31, lm = tid >> 5;
#pragma unroll
            for (int i = 0; i < 8; i++)
                Gs[lkk][lm + 8 * i] = G[(b0 + lm + 8 * i) * DIMH + kt + lkk];
#pragma unroll
            for (int i = 0; i < 4; i++) {
                int kk = (tid >> 5) + 8 * i;
                Ws[kk][j] = W[(kt + kk) * DIM + j];
            }
            __syncthreads();
#pragma unroll
            for (int p = 0; p < 32; p++) {
                float w = Ws[p][j];
#pragma unroll
                for (int i = 0; i < 8; i++) acc[i] += Gs[p][br + i] * w;
            }
            __syncthreads();
        }
    }
    float s0 = softplusf(w0p[0]), s1 = softplusf(w1p[0]);
    float wxo = Wxout[j];
#pragma unroll
    for (int i = 0; i < 8; i++) {
        int b = b0 + br + i;
        out[b * DIM + j] = s1 * (acc[i] + wxo) + s0 * xv[b * DIM + j];
    }
}

// ------------------------- M GEMM (mma.sync, A-tile 64 = 2 samples, B-tile 128 = r) --
__global__ __launch_bounds__(256, 2) void k_M_tc(
    const bf16* __restrict__ SWh,
    const bf16* __restrict__ Asrc, int aStride,
    const bf16* __restrict__ Dh,
    const float* __restrict__ Wxt,
    bf16* __restrict__ Mout)
{
    __shared__ __align__(16) bf16 As[64 * 40];
    __shared__ __align__(16) bf16 Bs[128 * 40];
    int r0 = blockIdx.x * 128, s0 = blockIdx.y * 2;
    int tid = threadIdx.x, lane = tid & 31, w = tid >> 5;
    int wm = w >> 2, wn = w & 3;
    int pm = tid >> 1, pk = (tid & 1) * 16;
    bool aStage = tid < 128;

    uint32_t asB = smemu32(As), bsB = smemu32(Bs);

    const bf16* aGl = aStage
        ? Asrc + (size_t)(s0 + (pm >> 5)) * aStride + (size_t)(pm & 31) * DIMH : Asrc;
    const bf16* dGl = aStage ? Dh + (size_t)(s0 + (pm >> 5)) * DIMH : Dh;
    const bf16* bGl = SWh + (size_t)(r0 + pm) * DIMH;

    float acc[2][4][4] = {};
    uint4 pa0, pa1, pd0, pd1, pb0, pb1;
    pb0 = *(const uint4*)(bGl + pk); pb1 = *(const uint4*)(bGl + pk + 8);
    if (aStage) {
        pa0 = *(const uint4*)(aGl + pk); pa1 = *(const uint4*)(aGl + pk + 8);
        pd0 = *(const uint4*)(dGl + pk); pd1 = *(const uint4*)(dGl + pk + 8);
    }

    int aRowL = (lane & 7) + ((lane >> 3) & 1) * 8;
    int aColL = (lane >> 4) * 8;
    int bl_ = lane & 15;
    int bRowL = bl_ & 7, bColL = ((bl_ >> 3) & 1) * 8;

    for (int ch = 0; ch < DIMH / 32; ch++) {
        if (aStage) {
            uint4 w0, w1;
            const bf162* av = (const bf162*)&pa0; const bf162* dv = (const bf162*)&pd0;
            bf162* ov = (bf162*)&w0;
#pragma unroll
            for (int h = 0; h < 4; h++) ov[h] = __hmul2(av[h], dv[h]);
            av = (const bf162*)&pa1; dv = (const bf162*)&pd1; ov = (bf162*)&w1;
#pragma unroll
            for (int h = 0; h < 4; h++) ov[h] = __hmul2(av[h], dv[h]);
            *(uint4*)&As[pm * 40 + pk] = w0; *(uint4*)&As[pm * 40 + pk + 8] = w1;
        }
        *(uint4*)&Bs[pm * 40 + pk] = pb0; *(uint4*)&Bs[pm * 40 + pk + 8] = pb1;
        __syncthreads();
        if (ch + 1 < DIMH / 32) {
            int kt = (ch + 1) * 32;
            pb0 = *(const uint4*)(bGl + kt + pk); pb1 = *(const uint4*)(bGl + kt + pk + 8);
            if (aStage) {
                pa0 = *(const uint4*)(aGl + kt + pk); pa1 = *(const uint4*)(aGl + kt + pk + 8);
                pd0 = *(const uint4*)(dGl + kt + pk); pd1 = *(const uint4*)(dGl + kt + pk + 8);
            }
        }
#pragma unroll
        for (int kk = 0; kk < 32; kk += 16) {
            uint32_t afr[2][4];
#pragma unroll
            for (int mi = 0; mi < 2; mi++) {
                int row = wm * 32 + mi * 16 + aRowL;
                LDSM4(afr[mi], asB + (uint32_t)(row * 40 + kk + aColL) * 2);
            }
            uint32_t bfr[4][2];
#pragma unroll
            for (int ni = 0; ni < 4; ni++) {
                int row = wn * 32 + ni * 8 + bRowL;
                LDSM2(bfr[ni], bsB + (uint32_t)(row * 40 + kk + bColL) * 2);
            }
#pragma unroll
            for (int mi = 0; mi < 2; mi++)
#pragma unroll
                for (int ni = 0; ni < 4; ni++)
                    MMA_BF16(acc[mi][ni], afr[mi], bfr[ni]);
        }
        __syncthreads();
    }

#pragma unroll
    for (int mi = 0; mi < 2; mi++) {
        int m0 = wm * 32 + mi * 16 + (lane >> 2);
        int sA = s0 + (m0 >> 5), jA = m0 & 31, jB = (m0 + 8) & 31;
#pragma unroll
        for (int ni = 0; ni < 4; ni++) {
            int r = r0 + wn * 32 + ni * 8 + (lane & 3) * 2;
            float2 wxa = *(const float2*)(Wxt + jA * DIMH + r);
            float2 wxb = *(const float2*)(Wxt + jB * DIMH + r);
            bf162 oa = __floats2bfloat162_rn(acc[mi][ni][0] + wxa.x,
                                             acc[mi][ni][1] + wxa.y);
            bf162 ob = __floats2bfloat162_rn(acc[mi][ni][2] + wxb.x,
                                             acc[mi][ni][3] + wxb.y);
            *(bf162*)&Mout[(size_t)(sA * DIM + jA) * DIMH + r] = oa;
            *(bf162*)&Mout[(size_t)(sA * DIM + jB) * DIMH + r] = ob;
        }
    }
}

// ------------------------- Hessian: syrk + Cholesky -------------------------
struct __align__(16) WarpBuf {
    union {
        bf16 stage[32 * 40];
        float H[32][33];
    };
};

__global__ __launch_bounds__(256) void k_hess_tc(
    const bf16* __restrict__ Wz0t_h,
    const float* __restrict__ w0p, const float* __restrict__ w1p,
    float* __restrict__ out)
{
    __shared__ WarpBuf wb[8];
    int w = threadIdx.x >> 5, lane = threadIdx.x & 31;
    int s = blockIdx.x * 8 + w;
    WarpBuf& buf = wb[w];
    uint32_t stBase = smemu32(buf.stage);

    float acc[2][4][4] = {};

    int aRowL = (lane & 7) + ((lane >> 3) & 1) * 8;
    int aColL = (lane >> 4) * 8;
    int bl_ = lane & 15;
    int bRowL = bl_ & 7, bColL = ((bl_ >> 3) & 1) * 8;

    for (int layer = 0; layer < 3; layer++) {
        const bf16* Msrc = layer == 0 ? Wz0t_h
            : (layer == 1 ? g_M1t + (size_t)s * (DIM * DIMH)
                          : g_M2t + (size_t)s * (DIM * DIMH));
        const float* vsrc = (layer == 0 ? g_V0 : (layer == 1 ? g_V1 : g_V2)) + s * DIMH;
        for (int kt = 0; kt < DIMH; kt += 32) {
            float sv = sqrtf(fmaxf(vsrc[kt + lane], 0.f));
            uint4 q[4];
            const uint4* mp = (const uint4*)(Msrc + lane * DIMH + kt);
            q[0] = mp[0]; q[1] = mp[1]; q[2] = mp[2]; q[3] = mp[3];
            uint32_t* wq = (uint32_t*)q;
#pragma unroll
            for (int p = 0; p < 16; p++) {
                float vx = __shfl_sync(0xffffffffu, sv, 2 * p);
                float vy = __shfl_sync(0xffffffffu, sv, 2 * p + 1);
                bf162 hv = *(bf162*)&wq[p];
                float2 f = __bfloat1622float2(hv);
                f.x *= vx; f.y *= vy;
                bf162 o = __floats2bfloat162_rn(f.x, f.y);
                wq[p] = *(uint32_t*)&o;
            }
            __syncwarp();
            *(uint4*)&buf.stage[lane * 40]      = q[0];
            *(uint4*)&buf.stage[lane * 40 + 8]  = q[1];
            *(uint4*)&buf.stage[lane * 40 + 16] = q[2];
            *(uint4*)&buf.stage[lane * 40 + 24] = q[3];
            __syncwarp();
#pragma unroll
            for (int kk = 0; kk < 32; kk += 16) {
                uint32_t afr[2][4];
#pragma unroll
                for (int mi = 0; mi < 2; mi++)
                    LDSM4(afr[mi], stBase + (uint32_t)((mi * 16 + aRowL) * 40 + kk + aColL) * 2);
                uint32_t bfr[4][2];
#pragma unroll
                for (int ni = 0; ni < 4; ni++)
                    LDSM2(bfr[ni], stBase + (uint32_t)((ni * 8 + bRowL) * 40 + kk + bColL) * 2);
#pragma unroll
                for (int mi = 0; mi < 2; mi++)
#pragma unroll
                    for (int ni = 0; ni < 4; ni++)
                        MMA_BF16(acc[mi][ni], afr[mi], bfr[ni]);
            }
        }
    }
    float s0v = softplusf(w0p[0]), s1v = softplusf(w1p[0]);
    __syncwarp();
#pragma unroll
    for (int mi = 0; mi < 2; mi++) {
        int row = mi * 16 + (lane >> 2);
#pragma unroll
        for (int ni = 0; ni < 4; ni++) {
            int col = ni * 8 + (lane & 3) * 2;
            buf.H[row][col]         = s1v * acc[mi][ni][0] + (row == col ? s0v : 0.f);
            buf.H[row][col + 1]     = s1v * acc[mi][ni][1] + (row == col + 1 ? s0v : 0.f);
            buf.H[row + 8][col]     = s1v * acc[mi][ni][2] + (row + 8 == col ? s0v : 0.f);
            buf.H[row + 8][col + 1] = s1v * acc[mi][ni][3] + (row + 8 == col + 1 ? s0v : 0.f);
        }
    }
    __syncwarp();
    int r = lane;
    float lsum = 0.f;
    for (int jc = 0; jc < 32; jc++) {
        float svv = 0.f;
        if (r >= jc) {
            svv = buf.H[r][jc];
            for (int p = 0; p < jc; p++) svv -= buf.H[r][p] * buf.H[jc][p];
        }
        float dj = __shfl_sync(0xffffffffu, svv, jc);
        dj = sqrtf(dj);
        if (r == jc) { buf.H[r][jc] = dj; lsum = logf(dj); }
        else if (r > jc) buf.H[r][jc] = svv / dj;
        __syncwarp();
    }
#pragma unroll
    for (int off = 16; off; off >>= 1)
        lsum += __shfl_xor_sync(0xffffffffu, lsum, off);
    if (r == 0) out[B * DIM + s] = 2.f * lsum;
}

// ------------------------- launch -------------------------
extern "C" void kernel_launch(void* const* d_in, const int* in_sizes, int n_in,
                              void* d_out, int out_size) {
    const float* x        = (const float*)d_in[0];
    const float* c        = (const float*)d_in[1];
    const float* w0       = (const float*)d_in[2];
    const float* w1       = (const float*)d_in[3];
    const float* Wz0_w    = (const float*)d_in[4];
    const float* Wz0_b    = (const float*)d_in[5];
    const float* Wc0_w    = (const float*)d_in[6];
    const float* Wc0_b    = (const float*)d_in[7];
    const float* an0_b    = (const float*)d_in[8];
    const float* an0_logs = (const float*)d_in[9];
    const float* Wz1_w    = (const float*)d_in[10];
    const float* Wz1_b    = (const float*)d_in[11];
    const float* Wx1_w    = (const float*)d_in[12];
    const float* Wx1_b    = (const float*)d_in[13];
    const float* Wc1_w    = (const float*)d_in[14];
    const float* Wc1_b    = (const float*)d_in[15];
    const float* an1_b    = (const float*)d_in[16];
    const float* an1_logs = (const float*)d_in[17];
    const float* Wz2_w    = (const float*)d_in[18];
    const float* Wz2_b    = (const float*)d_in[19];
    const float* Wx2_w    = (const float*)d_in[20];
    const float* Wx2_b    = (const float*)d_in[21];
    const float* Wc2_w    = (const float*)d_in[22];
    const float* Wc2_b    = (const float*)d_in[23];
    const float* an2_b    = (const float*)d_in[24];
    const float* an2_logs = (const float*)d_in[25];
    const float* Wzout_w  = (const float*)d_in[26];
    const float* Wxout_w  = (const float*)d_in[27];
    float* out = (float*)d_out;

#define SYM(v, s) cudaGetSymbolAddress((void**)&v, s)
    float *swout, *Wx1t, *Wx2t;
    float *D0, *E0, *D1, *E1, *G2, *V2, *G1, *V1, *G0, *V0;
    bf16 *D0h, *D1h, *Wz0th, *M1t, *M2t;
    bf16 *SW1hi, *SW1lo, *SW2hi, *SW2lo, *SW1thi, *SW1tlo, *SW2thi, *SW2tlo;
    bf16 *Wc0hi, *Wc0lo, *Wc1hi, *Wc1lo, *Wc2hi, *Wc2lo;
    bf16 *Wz0hi, *Wz0lo, *Wx1hi, *Wx1lo, *Wx2hi, *Wx2lo;
    bf16 *xhi, *xlo, *chi, *clo;
    bf16 *z0hi, *z0lo, *z1hi, *z1lo, *G2hi, *G2lo, *G1hi, *G1lo;
    SYM(swout, g_swout); SYM(Wx1t, g_Wx1t); SYM(Wx2t, g_Wx2t);
    SYM(D0, g_D0); SYM(E0, g_E0); SYM(D1, g_D1); SYM(E1, g_E1);
    SYM(D0h, g_D0h); SYM(D1h, g_D1h);
    SYM(G2, g_G2); SYM(V2, g_V2); SYM(G1, g_G1); SYM(V1, g_V1);
    SYM(G0, g_G0); SYM(V0, g_V0);
    SYM(Wz0th, g_Wz0t_h); SYM(M1t, g_M1t); SYM(M2t, g_M2t);
    SYM(SW1hi, g_SW1hi); SYM(SW1lo, g_SW1lo); SYM(SW2hi, g_SW2hi); SYM(SW2lo, g_SW2lo);
    SYM(SW1thi, g_SW1thi); SYM(SW1tlo, g_SW1tlo); SYM(SW2thi, g_SW2thi); SYM(SW2tlo, g_SW2tlo);
    SYM(Wc0hi, g_Wc0hi); SYM(Wc0lo, g_Wc0lo); SYM(Wc1hi, g_Wc1hi); SYM(Wc1lo, g_Wc1lo);
    SYM(Wc2hi, g_Wc2hi); SYM(Wc2lo, g_Wc2lo);
    SYM(Wz0hi, g_Wz0hi); SYM(Wz0lo, g_Wz0lo); SYM(Wx1hi, g_Wx1hi); SYM(Wx1lo, g_Wx1lo);
    SYM(Wx2hi, g_Wx2hi); SYM(Wx2lo, g_Wx2lo);
    SYM(xhi, g_xhi); SYM(xlo, g_xlo); SYM(chi, g_chi); SYM(clo, g_clo);
    SYM(z0hi, g_z0hi); SYM(z0lo, g_z0lo); SYM(z1hi, g_z1hi); SYM(z1lo, g_z1lo);
    SYM(G2hi, g_G2hi); SYM(G2lo, g_G2lo); SYM(G1hi, g_G1hi); SYM(G1lo, g_G1lo);
#undef SYM

    k_prep<<<1024, 256>>>(Wz1_w, Wz2_w, Wzout_w, Wz0_w, Wx1_w, Wx2_w);
    k_tr<<<dim3(32, 32, 4), dim3(32, 8)>>>();
    k_split<<<1024, 256>>>(c, x, Wc0_w, Wc1_w, Wc2_w);

    dim3 gt(DIMH / 128, B / 64);
    k_fwd_tc<<<gt, 256>>>(chi, clo, Wc0hi, Wc0lo, DIMC,
                          xhi, xlo, Wz0hi, Wz0lo, DIM,
                          nullptr, nullptr, nullptr, nullptr, 0,
                          Wc0_b, Wz0_b, nullptr, an0_b, an0_logs, nullptr,
                          z0hi, z0lo, D0, E0, D0h, nullptr, nullptr, nullptr, nullptr);
    k_fwd_tc<<<gt, 256>>>(z0hi, z0lo, SW1hi, SW1lo, DIMH,
                          chi, clo, Wc1hi, Wc1lo, DIMC,
                          xhi, xlo, Wx1hi, Wx1lo, DIM,
                          Wz1_b, Wc1_b, Wx1_b, an1_b, an1_logs, nullptr,
                          z1hi, z1lo, D1, E1, D1h, nullptr, nullptr, nullptr, nullptr);
    k_fwd_tc<<<gt, 256>>>(z1hi, z1lo, SW2hi, SW2lo, DIMH,
                          chi, clo, Wc2hi, Wc2lo, DIMC,
                          xhi, xlo, Wx2hi, Wx2lo, DIM,
                          Wz2_b, Wc2_b, Wx2_b, an2_b, an2_logs, swout,
                          nullptr, nullptr, nullptr, nullptr, nullptr, G2, G2hi, G2lo, V2);

    k_u_tc<<<gt, 256>>>(G2hi, G2lo, SW2thi, SW2tlo, D1, E1, G1, G1hi, G1lo, V1);
    k_u_tc<<<gt, 256>>>(G1hi, G1lo, SW1thi, SW1tlo, D0, E0, G0, nullptr, nullptr, V0);

    k_f<<<B / 64, 256>>>(x, Wz0_w, Wx1_w, Wx2_w, Wxout_w, w0, w1, out);

    dim3 gm(DIMH / 128, B / 2);
    k_M_tc<<<gm, 256>>>(SW1hi, Wz0th, 0,          D0h, Wx1t, M1t);
    k_M_tc<<<gm, 256>>>(SW2hi, M1t,   DIM * DIMH, D1h, Wx2t, M2t);

    k_hess_tc<<<B / 8, 256>>>(Wz0th, w0, w1, out);
}

// round 17
// speedup vs baseline: 1.1716x; 1.1716x over previous
#include <cuda_runtime.h>
#include <cuda_bf16.h>
#include <cstdint>

#define B 1024
#define DIM 32
#define DIMH 1024
#define DIMC 512

typedef __nv_bfloat16 bf16;
typedef __nv_bfloat162 bf162;

// ------------------------- device scratch -------------------------
__device__ float g_swout[DIMH];
__device__ bf16 g_Wz0t_h[DIM * DIMH];
__device__ float g_Wx1t[DIM * DIMH];
__device__ float g_Wx2t[DIM * DIMH];

__device__ bf16 g_SW1hi[DIMH * DIMH], g_SW1lo[DIMH * DIMH];
__device__ bf16 g_SW2hi[DIMH * DIMH], g_SW2lo[DIMH * DIMH];
__device__ bf16 g_SW1thi[DIMH * DIMH], g_SW1tlo[DIMH * DIMH];
__device__ bf16 g_SW2thi[DIMH * DIMH], g_SW2tlo[DIMH * DIMH];
__device__ bf16 g_Wc0hi[DIMH * DIMC], g_Wc0lo[DIMH * DIMC];
__device__ bf16 g_Wc1hi[DIMH * DIMC], g_Wc1lo[DIMH * DIMC];
__device__ bf16 g_Wc2hi[DIMH * DIMC], g_Wc2lo[DIMH * DIMC];
__device__ bf16 g_Wz0hi[DIMH * DIM], g_Wz0lo[DIMH * DIM];
__device__ bf16 g_Wx1hi[DIMH * DIM], g_Wx1lo[DIMH * DIM];
__device__ bf16 g_Wx2hi[DIMH * DIM], g_Wx2lo[DIMH * DIM];

__device__ bf16 g_xhi[B * DIM], g_xlo[B * DIM];
__device__ bf16 g_chi[B * DIMC], g_clo[B * DIMC];
__device__ bf16 g_z0hi[B * DIMH], g_z0lo[B * DIMH];
__device__ bf16 g_z1hi[B * DIMH], g_z1lo[B * DIMH];
__device__ bf16 g_G2hi[B * DIMH], g_G2lo[B * DIMH];
__device__ bf16 g_G1hi[B * DIMH], g_G1lo[B * DIMH];

__device__ float g_D0[B * DIMH], g_E0[B * DIMH];
__device__ float g_D1[B * DIMH], g_E1[B * DIMH];
__device__ bf16 g_D0h[B * DIMH], g_D1h[B * DIMH];
__device__ float g_G2[B * DIMH], g_V2[B * DIMH];
__device__ float g_G1[B * DIMH], g_V1[B * DIMH];
__device__ float g_G0[B * DIMH], g_V0[B * DIMH];

__device__ bf16 g_M1t[(size_t)B * DIM * DIMH];
__device__ bf16 g_M2t[(size_t)B * DIM * DIMH];

// ------------------------- math helpers -------------------------
__device__ __forceinline__ float softplusf(float x) {
    return x > 20.f ? x : log1pf(expf(x));
}
__device__ __forceinline__ float gspf(float x) {
    const float SHP = 1.2533141373155003f;
    float ex = expf(-0.5f * x * x);
    float er = erff(x * 0.7071067811865475f);
    return (SHP * x * er + ex + SHP * x) * (1.0f / (2.0f * SHP));
}
__device__ __forceinline__ float ncdf(float x) {
    return 0.5f * (1.f + erff(x * 0.7071067811865475f));
}
__device__ __forceinline__ float npdf(float x) {
    return 0.3989422804014327f * expf(-0.5f * x * x);
}
__device__ __forceinline__ void bsplit(float v, bf16& h, bf16& l) {
    h = __float2bfloat16(v);
    l = __float2bfloat16(v - __bfloat162float(h));
}
__device__ __forceinline__ uint32_t smemu32(const void* p) {
    uint32_t a;
    asm("{ .reg .u64 t; cvta.to.shared.u64 t, %1; cvt.u32.u64 %0, t; }" : "=r"(a) : "l"(p));
    return a;
}

#define LDSM4(F, ADDR) asm volatile( \
    "ldmatrix.sync.aligned.m8n8.x4.shared.b16 {%0,%1,%2,%3}, [%4];" \
    : "=r"((F)[0]), "=r"((F)[1]), "=r"((F)[2]), "=r"((F)[3]) : "r"(ADDR))
#define LDSM2(F, ADDR) asm volatile( \
    "ldmatrix.sync.aligned.m8n8.x2.shared.b16 {%0,%1}, [%2];" \
    : "=r"((F)[0]), "=r"((F)[1]) : "r"(ADDR))
#define MMA_BF16(ACC, AF, BF) asm volatile( \
    "mma.sync.aligned.m16n8k16.row.col.f32.bf16.bf16.f32 " \
    "{%0,%1,%2,%3}, {%4,%5,%6,%7}, {%8,%9}, {%0,%1,%2,%3};" \
    : "+f"((ACC)[0]), "+f"((ACC)[1]), "+f"((ACC)[2]), "+f"((ACC)[3]) \
    : "r"((AF)[0]), "r"((AF)[1]), "r"((AF)[2]), "r"((AF)[3]), \
      "r"((BF)[0]), "r"((BF)[1]))

// ------------------------- prep -------------------------
__global__ void k_prep(const float* __restrict__ Wz1, const float* __restrict__ Wz2,
                       const float* __restrict__ Wzout,
                       const float* __restrict__ Wz0, const float* __restrict__ Wx1,
                       const float* __restrict__ Wx2) {
    int n = DIMH * DIMH;
    for (int i = blockIdx.x * blockDim.x + threadIdx.x; i < n; i += gridDim.x * blockDim.x) {
        float s1 = softplusf(Wz1[i]) * (1.f / DIMH);
        float s2 = softplusf(Wz2[i]) * (1.f / DIMH);
        bsplit(s1, g_SW1hi[i], g_SW1lo[i]);
        bsplit(s2, g_SW2hi[i], g_SW2lo[i]);
        if (i < DIMH) g_swout[i] = softplusf(Wzout[i]) * (1.f / DIMH);
        if (i < DIM * DIMH) {
            int k = i >> 5, j = i & 31;
            g_Wz0t_h[j * DIMH + k] = __float2bfloat16(Wz0[i]);
            g_Wx1t[j * DIMH + k] = Wx1[i];
            g_Wx2t[j * DIMH + k] = Wx2[i];
            bsplit(Wz0[i], g_Wz0hi[i], g_Wz0lo[i]);
            bsplit(Wx1[i], g_Wx1hi[i], g_Wx1lo[i]);
            bsplit(Wx2[i], g_Wx2hi[i], g_Wx2lo[i]);
        }
    }
}

__global__ void k_split(const float* __restrict__ cv, const float* __restrict__ xv,
                        const float* __restrict__ Wc0, const float* __restrict__ Wc1,
                        const float* __restrict__ Wc2) {
    int n = DIMH * DIMC;
    for (int i = blockIdx.x * blockDim.x + threadIdx.x; i < n; i += gridDim.x * blockDim.x) {
        bsplit(cv[i], g_chi[i], g_clo[i]);
        bsplit(Wc0[i], g_Wc0hi[i], g_Wc0lo[i]);
        bsplit(Wc1[i], g_Wc1hi[i], g_Wc1lo[i]);
        bsplit(Wc2[i], g_Wc2hi[i], g_Wc2lo[i]);
        if (i < B * DIM) bsplit(xv[i], g_xhi[i], g_xlo[i]);
    }
}

__global__ void k_tr() {
    __shared__ bf16 t[32][33];
    const bf16* src; bf16* dst;
    switch (blockIdx.z) {
        case 0: src = g_SW1hi; dst = g_SW1thi; break;
        case 1: src = g_SW1lo; dst = g_SW1tlo; break;
        case 2: src = g_SW2hi; dst = g_SW2thi; break;
        default: src = g_SW2lo; dst = g_SW2tlo; break;
    }
    int jx = blockIdx.x * 32, ky = blockIdx.y * 32;
    int tx = threadIdx.x, ty = threadIdx.y;
#pragma unroll
    for (int r = 0; r < 4; r++)
        t[ty + 8 * r][tx] = src[(ky + ty + 8 * r) * DIMH + jx + tx];
    __syncthreads();
#pragma unroll
    for (int r = 0; r < 4; r++)
        dst[(jx + ty + 8 * r) * DIMH + ky + tx] = t[tx][ty + 8 * r];
}

// ------------------------- split-bf16 forward layer (A-tile 64, B-tile 128) ----------
__global__ __launch_bounds__(256, 2) void k_fwd_tc(
    const bf16* __restrict__ A1hi, const bf16* __restrict__ A1lo,
    const bf16* __restrict__ B1hi, const bf16* __restrict__ B1lo, int K1,
    const bf16* __restrict__ A2hi, const bf16* __restrict__ A2lo,
    const bf16* __restrict__ B2hi, const bf16* __restrict__ B2lo, int K2,
    const bf16* __restrict__ A3hi, const bf16* __restrict__ A3lo,
    const bf16* __restrict__ B3hi, const bf16* __restrict__ B3lo, int K3,
    const float* __restrict__ bias1, const float* __restrict__ bias2,
    const float* __restrict__ bias3,
    const float* __restrict__ an_b, const float* __restrict__ an_logs,
    const float* __restrict__ swout,
    bf16* __restrict__ zhi, bf16* __restrict__ zlo,
    float* __restrict__ outD, float* __restrict__ outE, bf16* __restrict__ outDh,
    float* __restrict__ outG, bf16* __restrict__ ghi, bf16* __restrict__ glo,
    float* __restrict__ outV)
{
    __shared__ __align__(16) bf16 Ah_s[64 * 40], Al_s[64 * 40];
    __shared__ __align__(16) bf16 Bh_s[128 * 40], Bl_s[128 * 40];
    int k0 = blockIdx.x * 128, b0 = blockIdx.y * 64;
    int tid = threadIdx.x, lane = tid & 31, w = tid >> 5;
    int wm = w >> 2, wn = w & 3;
    int pm = tid >> 1, pk = (tid & 1) * 16;
    bool aStage = tid < 128;

    int n1 = K1 >> 5, n2 = K2 >> 5, n3 = K3 >> 5;
    int nCh = n1 + n2 + n3;

    uint32_t ahB = smemu32(Ah_s), alB = smemu32(Al_s);
    uint32_t bhB = smemu32(Bh_s), blB = smemu32(Bl_s);

    float acc[2][4][4] = {};
    uint4 rA0, rA1, rL0, rL1, rB0, rB1, rM0, rM1;

    auto loadCh = [&](int ch) {
        const bf16 *Ah, *Al, *Bh, *Bl; int K, kt;
        if (ch < n1)            { Ah = A1hi; Al = A1lo; Bh = B1hi; Bl = B1lo; K = K1; kt = ch << 5; }
        else if (ch < n1 + n2)  { Ah = A2hi; Al = A2lo; Bh = B2hi; Bl = B2lo; K = K2; kt = (ch - n1) << 5; }
        else                    { Ah = A3hi; Al = A3lo; Bh = B3hi; Bl = B3lo; K = K3; kt = (ch - n1 - n2) << 5; }
        size_t bo = (size_t)(k0 + pm) * K + kt + pk;
        rB0 = *(const uint4*)(Bh + bo); rB1 = *(const uint4*)(Bh + bo + 8);
        rM0 = *(const uint4*)(Bl + bo); rM1 = *(const uint4*)(Bl + bo + 8);
        if (aStage) {
            size_t ao = (size_t)(b0 + pm) * K + kt + pk;
            rA0 = *(const uint4*)(Ah + ao); rA1 = *(const uint4*)(Ah + ao + 8);
            rL0 = *(const uint4*)(Al + ao); rL1 = *(const uint4*)(Al + ao + 8);
        }
    };

    int aRowL = (lane & 7) + ((lane >> 3) & 1) * 8;
    int aColL = (lane >> 4) * 8;
    int bl_ = lane & 15;
    int bRowL = bl_ & 7, bColL = ((bl_ >> 3) & 1) * 8;

    loadCh(0);
    for (int ch = 0; ch < nCh; ch++) {
        if (aStage) {
            *(uint4*)&Ah_s[pm * 40 + pk] = rA0; *(uint4*)&Ah_s[pm * 40 + pk + 8] = rA1;
            *(uint4*)&Al_s[pm * 40 + pk] = rL0; *(uint4*)&Al_s[pm * 40 + pk + 8] = rL1;
        }
        *(uint4*)&Bh_s[pm * 40 + pk] = rB0; *(uint4*)&Bh_s[pm * 40 + pk + 8] = rB1;
        *(uint4*)&Bl_s[pm * 40 + pk] = rM0; *(uint4*)&Bl_s[pm * 40 + pk + 8] = rM1;
        __syncthreads();
        if (ch + 1 < nCh) loadCh(ch + 1);
#pragma unroll
        for (int kk = 0; kk < 32; kk += 16) {
            uint32_t ah[2][4], al[2][4];
#pragma unroll
            for (int mi = 0; mi < 2; mi++) {
                int row = wm * 32 + mi * 16 + aRowL;
                LDSM4(ah[mi], ahB + (uint32_t)(row * 40 + kk + aColL) * 2);
                LDSM4(al[mi], alB + (uint32_t)(row * 40 + kk + aColL) * 2);
            }
            uint32_t bh[4][2], bl2[4][2];
#pragma unroll
            for (int ni = 0; ni < 4; ni++) {
                int row = wn * 32 + ni * 8 + bRowL;
                LDSM2(bh[ni], bhB + (uint32_t)(row * 40 + kk + bColL) * 2);
                LDSM2(bl2[ni], blB + (uint32_t)(row * 40 + kk + bColL) * 2);
            }
#pragma unroll
            for (int mi = 0; mi < 2; mi++)
#pragma unroll
                for (int ni = 0; ni < 4; ni++) {
                    MMA_BF16(acc[mi][ni], ah[mi], bh[ni]);
                    MMA_BF16(acc[mi][ni], ah[mi], bl2[ni]);
                    MMA_BF16(acc[mi][ni], al[mi], bh[ni]);
                }
        }
        __syncthreads();
    }

    bool gmode = (swout != nullptr);
#pragma unroll
    for (int mi = 0; mi < 2; mi++) {
        int m0 = wm * 32 + mi * 16 + (lane >> 2);
        int bA = b0 + m0, bB = b0 + m0 + 8;
#pragma unroll
        for (int ni = 0; ni < 4; ni++) {
            int k = k0 + wn * 32 + ni * 8 + (lane & 3) * 2;
            float2 bb1 = *(const float2*)(bias1 + k);
            float2 bb2 = *(const float2*)(bias2 + k);
            float2 bb3 = bias3 ? *(const float2*)(bias3 + k) : make_float2(0.f, 0.f);
            float2 ab = *(const float2*)(an_b + k);
            float2 alg = *(const float2*)(an_logs + k);
            float aa0 = expf(alg.x), aa1 = expf(alg.y);
            float h00 = acc[mi][ni][0] + bb1.x + bb2.x + bb3.x;
            float h01 = acc[mi][ni][1] + bb1.y + bb2.y + bb3.y;
            float h10 = acc[mi][ni][2] + bb1.x + bb2.x + bb3.x;
            float h11 = acc[mi][ni][3] + bb1.y + bb2.y + bb3.y;
            float p00 = (h00 + ab.x) * aa0, p01 = (h01 + ab.y) * aa1;
            float p10 = (h10 + ab.x) * aa0, p11 = (h11 + ab.y) * aa1;
            float d00 = aa0 * ncdf(p00), d01 = aa1 * ncdf(p01);
            float d10 = aa0 * ncdf(p10), d11 = aa1 * ncdf(p11);
            float e00 = aa0 * aa0 * npdf(p00), e01 = aa1 * aa1 * npdf(p01);
            float e10 = aa0 * aa0 * npdf(p10), e11 = aa1 * aa1 * npdf(p11);
            if (!gmode) {
                float z00 = gspf(p00), z01 = gspf(p01);
                float z10 = gspf(p10), z11 = gspf(p11);
                bf162 zh, zl;
                bsplit(z00, zh.x, zl.x); bsplit(z01, zh.y, zl.y);
                *(bf162*)&zhi[(size_t)bA * DIMH + k] = zh;
                *(bf162*)&zlo[(size_t)bA * DIMH + k] = zl;
                bsplit(z10, zh.x, zl.x); bsplit(z11, zh.y, zl.y);
                *(bf162*)&zhi[(size_t)bB * DIMH + k] = zh;
                *(bf162*)&zlo[(size_t)bB * DIMH + k] = zl;
                *(float2*)&outD[(size_t)bA * DIMH + k] = make_float2(d00, d01);
                *(float2*)&outD[(size_t)bB * DIMH + k] = make_float2(d10, d11);
                *(float2*)&outE[(size_t)bA * DIMH + k] = make_float2(e00, e01);
                *(float2*)&outE[(size_t)bB * DIMH + k] = make_float2(e10, e11);
                *(bf162*)&outDh[(size_t)bA * DIMH + k] = __floats2bfloat162_rn(d00, d01);
                *(bf162*)&outDh[(size_t)bB * DIMH + k] = __floats2bfloat162_rn(d10, d11);
            } else {
                float2 so = *(const float2*)(swout + k);
                float g00 = so.x * d00, g01 = so.y * d01;
                float g10 = so.x * d10, g11 = so.y * d11;
                *(float2*)&outG[(size_t)bA * DIMH + k] = make_float2(g00, g01);
                *(float2*)&outG[(size_t)bB * DIMH + k] = make_float2(g10, g11);
                *(float2*)&outV[(size_t)bA * DIMH + k] = make_float2(so.x * e00, so.y * e01);
                *(float2*)&outV[(size_t)bB * DIMH + k] = make_float2(so.x * e10, so.y * e11);
                bf162 gh, gl;
                bsplit(g00, gh.x, gl.x); bsplit(g01, gh.y, gl.y);
                *(bf162*)&ghi[(size_t)bA * DIMH + k] = gh;
                *(bf162*)&glo[(size_t)bA * DIMH + k] = gl;
                bsplit(g10, gh.x, gl.x); bsplit(g11, gh.y, gl.y);
                *(bf162*)&ghi[(size_t)bB * DIMH + k] = gh;
                *(bf162*)&glo[(size_t)bB * DIMH + k] = gl;
            }
        }
    }
}

// ------------------------- split-bf16 backward u (A-tile 64, B-tile 128) -------------
__global__ __launch_bounds__(256, 2) void k_u_tc(
    const bf16* __restrict__ Ghi, const bf16* __restrict__ Glo,
    const bf16* __restrict__ SWthi, const bf16* __restrict__ SWtlo,
    const float* __restrict__ dvec, const float* __restrict__ evec,
    float* __restrict__ outG, bf16* __restrict__ ghi, bf16* __restrict__ glo,
    float* __restrict__ outV)
{
    __shared__ __align__(16) bf16 Ah_s[64 * 40], Al_s[64 * 40];
    __shared__ __align__(16) bf16 Bh_s[128 * 40], Bl_s[128 * 40];
    int j0 = blockIdx.x * 128, b0 = blockIdx.y * 64;
    int tid = threadIdx.x, lane = tid & 31, w = tid >> 5;
    int wm = w >> 2, wn = w & 3;
    int pm = tid >> 1, pk = (tid & 1) * 16;
    bool aStage = tid < 128;

    uint32_t ahB = smemu32(Ah_s), alB = smemu32(Al_s);
    uint32_t bhB = smemu32(Bh_s), blB = smemu32(Bl_s);

    const bf16* aH = Ghi + (size_t)(b0 + pm) * DIMH;
    const bf16* aL = Glo + (size_t)(b0 + pm) * DIMH;
    const bf16* bH = SWthi + (size_t)(j0 + pm) * DIMH;
    const bf16* bL = SWtlo + (size_t)(j0 + pm) * DIMH;

    float acc[2][4][4] = {};
    uint4 rA0, rA1, rL0, rL1, rB0, rB1, rM0, rM1;
    rB0 = *(const uint4*)(bH + pk); rB1 = *(const uint4*)(bH + pk + 8);
    rM0 = *(const uint4*)(bL + pk); rM1 = *(const uint4*)(bL + pk + 8);
    if (aStage) {
        rA0 = *(const uint4*)(aH + pk); rA1 = *(const uint4*)(aH + pk + 8);
        rL0 = *(const uint4*)(aL + pk); rL1 = *(const uint4*)(aL + pk + 8);
    }

    int aRowL = (lane & 7) + ((lane >> 3) & 1) * 8;
    int aColL = (lane >> 4) * 8;
    int bl_ = lane & 15;
    int bRowL = bl_ & 7, bColL = ((bl_ >> 3) & 1) * 8;

    for (int ch = 0; ch < DIMH / 32; ch++) {
        if (aStage) {
            *(uint4*)&Ah_s[pm * 40 + pk] = rA0; *(uint4*)&Ah_s[pm * 40 + pk + 8] = rA1;
            *(uint4*)&Al_s[pm * 40 + pk] = rL0; *(uint4*)&Al_s[pm * 40 + pk + 8] = rL1;
        }
        *(uint4*)&Bh_s[pm * 40 + pk] = rB0; *(uint4*)&Bh_s[pm * 40 + pk + 8] = rB1;
        *(uint4*)&Bl_s[pm * 40 + pk] = rM0; *(uint4*)&Bl_s[pm * 40 + pk + 8] = rM1;
        __syncthreads();
        if (ch + 1 < DIMH / 32) {
            int kt = (ch + 1) * 32;
            rB0 = *(const uint4*)(bH + kt + pk); rB1 = *(const uint4*)(bH + kt + pk + 8);
            rM0 = *(const uint4*)(bL + kt + pk); rM1 = *(const uint4*)(bL + kt + pk + 8);
            if (aStage) {
                rA0 = *(const uint4*)(aH + kt + pk); rA1 = *(const uint4*)(aH + kt + pk + 8);
                rL0 = *(const uint4*)(aL + kt + pk); rL1 = *(const uint4*)(aL + kt + pk + 8);
            }
        }
#pragma unroll
        for (int kk = 0; kk < 32; kk += 16) {
            uint32_t ah[2][4], al[2][4];
#pragma unroll
            for (int mi = 0; mi < 2; mi++) {
                int row = wm * 32 + mi * 16 + aRowL;
                LDSM4(ah[mi], ahB + (uint32_t)(row * 40 + kk + aColL) * 2);
                LDSM4(al[mi], alB + (uint32_t)(row * 40 + kk + aColL) * 2);
            }
            uint32_t bh[4][2], bl2[4][2];
#pragma unroll
            for (int ni = 0; ni < 4; ni++) {
                int row = wn * 32 + ni * 8 + bRowL;
                LDSM2(bh[ni], bhB + (uint32_t)(row * 40 + kk + bColL) * 2);
                LDSM2(bl2[ni], blB + (uint32_t)(row * 40 + kk + bColL) * 2);
            }
#pragma unroll
            for (int mi = 0; mi < 2; mi++)
#pragma unroll
                for (int ni = 0; ni < 4; ni++) {
                    MMA_BF16(acc[mi][ni], ah[mi], bh[ni]);
                    MMA_BF16(acc[mi][ni], ah[mi], bl2[ni]);
                    MMA_BF16(acc[mi][ni], al[mi], bh[ni]);
                }
        }
        __syncthreads();
    }

#pragma unroll
    for (int mi = 0; mi < 2; mi++) {
        int m0 = wm * 32 + mi * 16 + (lane >> 2);
        int bA = b0 + m0, bB = b0 + m0 + 8;
#pragma unroll
        for (int ni = 0; ni < 4; ni++) {
            int j = j0 + wn * 32 + ni * 8 + (lane & 3) * 2;
            float2 dA = *(const float2*)&dvec[(size_t)bA * DIMH + j];
            float2 dB = *(const float2*)&dvec[(size_t)bB * DIMH + j];
            float2 eA = *(const float2*)&evec[(size_t)bA * DIMH + j];
            float2 eB = *(const float2*)&evec[(size_t)bB * DIMH + j];
            float u00 = acc[mi][ni][0], u01 = acc[mi][ni][1];
            float u10 = acc[mi][ni][2], u11 = acc[mi][ni][3];
            float g00 = u00 * dA.x, g01 = u01 * dA.y;
            float g10 = u10 * dB.x, g11 = u11 * dB.y;
            *(float2*)&outG[(size_t)bA * DIMH + j] = make_float2(g00, g01);
            *(float2*)&outG[(size_t)bB * DIMH + j] = make_float2(g10, g11);
            *(float2*)&outV[(size_t)bA * DIMH + j] =
                make_float2(fmaxf(u00 * eA.x, 0.f), fmaxf(u01 * eA.y, 0.f));
            *(float2*)&outV[(size_t)bB * DIMH + j] =
                make_float2(fmaxf(u10 * eB.x, 0.f), fmaxf(u11 * eB.y, 0.f));
            if (ghi) {
                bf162 gh, gl;
                bsplit(g00, gh.x, gl.x); bsplit(g01, gh.y, gl.y);
                *(bf162*)&ghi[(size_t)bA * DIMH + j] = gh;
                *(bf162*)&glo[(size_t)bA * DIMH + j] = gl;
                bsplit(g10, gh.x, gl.x); bsplit(g11, gh.y, gl.y);
                *(bf162*)&ghi[(size_t)bB * DIMH + j] = gh;
                *(bf162*)&glo[(size_t)bB * DIMH + j] = gl;
            }
        }
    }
}

// ------------------------- f output (SIMT, fp32) -------------------------
__global__ __launch_bounds__(256) void k_f(
    const float* __restrict__ xv,
    const float* __restrict__ Wz0, const float* __restrict__ Wx1,
    const float* __restrict__ Wx2, const float* __restrict__ Wxout,
    const float* __restrict__ w0p, const float* __restrict__ w1p,
    float* __restrict__ out)
{
    __shared__ float Gs[32][65];
    __shared__ float Ws[32][33];
    int b0 = blockIdx.x * 64;
    int tid = threadIdx.x;
    int j = tid & 31;
    int br = (tid >> 5) * 8;
    float acc[8] = {};

    for (int seg = 0; seg < 3; seg++) {
        const float* G = seg == 0 ? g_G0 : (seg == 1 ? g_G1 : g_G2);
        const float* W = seg == 0 ? Wz0  : (seg == 1 ? Wx1  : Wx2);
        for (int kt = 0; kt < DIMH; kt += 32) {
            int lkk = tid & 31, lm = tid >> 5;
#pragma unroll
            for (int i = 0; i < 8; i++)
                Gs[lkk][lm + 8 * i] = G[(b0 + lm + 8 * i) * DIMH + kt + lkk];
#pragma unroll
            for (int i = 0; i < 4; i++) {
                int kk = (tid >> 5) + 8 * i;
                Ws[kk][j] = W[(kt + kk) * DIM + j];
            }
            __syncthreads();
#pragma unroll
            for (int p = 0; p < 32; p++) {
                float w = Ws[p][j];
#pragma unroll
                for (int i = 0; i < 8; i++) acc[i] += Gs[p][br + i] * w;
            }
            __syncthreads();
        }
    }
    float s0 = softplusf(w0p[0]), s1 = softplusf(w1p[0]);
    float wxo = Wxout[j];
#pragma unroll
    for (int i = 0; i < 8; i++) {
        int b = b0 + br + i;
        out[b * DIM + j] = s1 * (acc[i] + wxo) + s0 * xv[b * DIM + j];
    }
}

// ------------------------- M GEMM (R9-proven: 128x128 tile, 4 samples/CTA) -----------
__global__ __launch_bounds__(256) void k_M_tc(
    const bf16* __restrict__ SWh,
    const bf16* __restrict__ Asrc,
    int aSampleStride,
    const float* __restrict__ Dvec,
    const float* __restrict__ Wxt,
    bf16* __restrict__ Mout)
{
    __shared__ __align__(16) bf16 As[128 * 40];
    __shared__ __align__(16) bf16 Bs[128 * 40];
    int r0 = blockIdx.x * 128;
    int s0 = blockIdx.y * 4;
    int tid = threadIdx.x;
    int lane = tid & 31, w = tid >> 5;
    int wm = w >> 1, wn = w & 1;

    int pm = tid >> 1;
    int pk = (tid & 1) * 16;
    int ps = s0 + (pm >> 5), pj = pm & 31;
    const bf16* aRow = Asrc + (size_t)ps * aSampleStride + pj * DIMH;
    const float* dRow = Dvec + ps * DIMH;
    const bf16* bRow = SWh + (size_t)(r0 + pm) * DIMH;

    uint32_t asBase = smemu32(As);
    uint32_t bsBase = smemu32(Bs);

    float acc[2][8][4] = {};

    uint4 aReg[2], bReg[2];
    float4 dReg[4];
    {
        const uint4* ap = (const uint4*)(aRow + pk);
        aReg[0] = ap[0]; aReg[1] = ap[1];
        const float4* dp = (const float4*)(dRow + pk);
        dReg[0] = dp[0]; dReg[1] = dp[1]; dReg[2] = dp[2]; dReg[3] = dp[3];
        const uint4* bp = (const uint4*)(bRow + pk);
        bReg[0] = bp[0]; bReg[1] = bp[1];
    }

    int aRowL = (lane & 7) + ((lane >> 3) & 1) * 8;
    int aColL = (lane >> 4) * 8;
    int bl_ = lane & 15;
    int bRowL = bl_ & 7;
    int bColL = ((bl_ >> 3) & 1) * 8;

    for (int t = 0; t < DIMH / 32; t++) {
        {
            const float* dv = (const float*)dReg;
            uint4 outw[2];
#pragma unroll
            for (int h = 0; h < 2; h++) {
                uint32_t* src = (uint32_t*)&aReg[h];
                uint32_t* dst = (uint32_t*)&outw[h];
#pragma unroll
                for (int q = 0; q < 4; q++) {
                    bf162 hv = *(bf162*)&src[q];
                    float2 f = __bfloat1622float2(hv);
                    f.x *= dv[h * 8 + q * 2];
                    f.y *= dv[h * 8 + q * 2 + 1];
                    bf162 o = __floats2bfloat162_rn(f.x, f.y);
                    dst[q] = *(uint32_t*)&o;
                }
            }
            *(uint4*)&As[pm * 40 + pk]     = outw[0];
            *(uint4*)&As[pm * 40 + pk + 8] = outw[1];
            *(uint4*)&Bs[pm * 40 + pk]     = bReg[0];
            *(uint4*)&Bs[pm * 40 + pk + 8] = bReg[1];
        }
        __syncthreads();
        if (t + 1 < DIMH / 32) {
            int kt2 = (t + 1) * 32;
            const uint4* ap = (const uint4*)(aRow + kt2 + pk);
            aReg[0] = ap[0]; aReg[1] = ap[1];
            const float4* dp = (const float4*)(dRow + kt2 + pk);
            dReg[0] = dp[0]; dReg[1] = dp[1]; dReg[2] = dp[2]; dReg[3] = dp[3];
            const uint4* bp = (const uint4*)(bRow + kt2 + pk);
            bReg[0] = bp[0]; bReg[1] = bp[1];
        }
#pragma unroll
        for (int kk = 0; kk < 32; kk += 16) {
            uint32_t afr[2][4];
#pragma unroll
            for (int mi = 0; mi < 2; mi++) {
                int row = wm * 32 + mi * 16 + aRowL;
                LDSM4(afr[mi], asBase + (uint32_t)(row * 40 + kk + aColL) * 2);
            }
            uint32_t bfr[8][2];
#pragma unroll
            for (int ni = 0; ni < 8; ni++) {
                int row = wn * 64 + ni * 8 + bRowL;
                LDSM2(bfr[ni], bsBase + (uint32_t)(row * 40 + kk + bColL) * 2);
            }
#pragma unroll
            for (int mi = 0; mi < 2; mi++)
#pragma unroll
                for (int ni = 0; ni < 8; ni++)
                    MMA_BF16(acc[mi][ni], afr[mi], bfr[ni]);
        }
        __syncthreads();
    }
#pragma unroll
    for (int mi = 0; mi < 2; mi++) {
        int m0 = wm * 32 + mi * 16 + (lane >> 2);
        int sA = s0 + (m0 >> 5), jA = m0 & 31;
        int jB = (m0 + 8) & 31;
#pragma unroll
        for (int ni = 0; ni < 8; ni++) {
            int r = r0 + wn * 64 + ni * 8 + (lane & 3) * 2;
            float2 wxa = *(const float2*)(Wxt + jA * DIMH + r);
            float2 wxb = *(const float2*)(Wxt + jB * DIMH + r);
            bf162 oa = __floats2bfloat162_rn(acc[mi][ni][0] + wxa.x,
                                             acc[mi][ni][1] + wxa.y);
            bf162 ob = __floats2bfloat162_rn(acc[mi][ni][2] + wxb.x,
                                             acc[mi][ni][3] + wxb.y);
            *(bf162*)&Mout[(size_t)(sA * DIM + jA) * DIMH + r] = oa;
            *(bf162*)&Mout[(size_t)(sA * DIM + jB) * DIMH + r] = ob;
        }
    }
}

// ------------------------- Hessian: syrk + Cholesky -------------------------
struct __align__(16) WarpBuf {
    union {
        bf16 stage[32 * 40];
        float H[32][33];
    };
};

__global__ __launch_bounds__(256) void k_hess_tc(
    const bf16* __restrict__ Wz0t_h,
    const float* __restrict__ w0p, const float* __restrict__ w1p,
    float* __restrict__ out)
{
    __shared__ WarpBuf wb[8];
    int w = threadIdx.x >> 5, lane = threadIdx.x & 31;
    int s = blockIdx.x * 8 + w;
    WarpBuf& buf = wb[w];
    uint32_t stBase = smemu32(buf.stage);

    float acc[2][4][4] = {};

    int aRowL = (lane & 7) + ((lane >> 3) & 1) * 8;
    int aColL = (lane >> 4) * 8;
    int bl_ = lane & 15;
    int bRowL = bl_ & 7, bColL = ((bl_ >> 3) & 1) * 8;

    for (int layer = 0; layer < 3; layer++) {
        const bf16* Msrc = layer == 0 ? Wz0t_h
            : (layer == 1 ? g_M1t + (size_t)s * (DIM * DIMH)
                          : g_M2t + (size_t)s * (DIM * DIMH));
        const float* vsrc = (layer == 0 ? g_V0 : (layer == 1 ? g_V1 : g_V2)) + s * DIMH;
        for (int kt = 0; kt < DIMH; kt += 32) {
            float sv = sqrtf(fmaxf(vsrc[kt + lane], 0.f));
            uint4 q[4];
            const uint4* mp = (const uint4*)(Msrc + lane * DIMH + kt);
            q[0] = mp[0]; q[1] = mp[1]; q[2] = mp[2]; q[3] = mp[3];
            uint32_t* wq = (uint32_t*)q;
#pragma unroll
            for (int p = 0; p < 16; p++) {
                float vx = __shfl_sync(0xffffffffu, sv, 2 * p);
                float vy = __shfl_sync(0xffffffffu, sv, 2 * p + 1);
                bf162 hv = *(bf162*)&wq[p];
                float2 f = __bfloat1622float2(hv);
                f.x *= vx; f.y *= vy;
                bf162 o = __floats2bfloat162_rn(f.x, f.y);
                wq[p] = *(uint32_t*)&o;
            }
            __syncwarp();
            *(uint4*)&buf.stage[lane * 40]      = q[0];
            *(uint4*)&buf.stage[lane * 40 + 8]  = q[1];
            *(uint4*)&buf.stage[lane * 40 + 16] = q[2];
            *(uint4*)&buf.stage[lane * 40 + 24] = q[3];
            __syncwarp();
#pragma unroll
            for (int kk = 0; kk < 32; kk += 16) {
                uint32_t afr[2][4];
#pragma unroll
                for (int mi = 0; mi < 2; mi++)
                    LDSM4(afr[mi], stBase + (uint32_t)((mi * 16 + aRowL) * 40 + kk + aColL) * 2);
                uint32_t bfr[4][2];
#pragma unroll
                for (int ni = 0; ni < 4; ni++)
                    LDSM2(bfr[ni], stBase + (uint32_t)((ni * 8 + bRowL) * 40 + kk + bColL) * 2);
#pragma unroll
                for (int mi = 0; mi < 2; mi++)
#pragma unroll
                    for (int ni = 0; ni < 4; ni++)
                        MMA_BF16(acc[mi][ni], afr[mi], bfr[ni]);
            }
        }
    }
    float s0v = softplusf(w0p[0]), s1v = softplusf(w1p[0]);
    __syncwarp();
#pragma unroll
    for (int mi = 0; mi < 2; mi++) {
        int row = mi * 16 + (lane >> 2);
#pragma unroll
        for (int ni = 0; ni < 4; ni++) {
            int col = ni * 8 + (lane & 3) * 2;
            buf.H[row][col]         = s1v * acc[mi][ni][0] + (row == col ? s0v : 0.f);
            buf.H[row][col + 1]     = s1v * acc[mi][ni][1] + (row == col + 1 ? s0v : 0.f);
            buf.H[row + 8][col]     = s1v * acc[mi][ni][2] + (row + 8 == col ? s0v : 0.f);
            buf.H[row + 8][col + 1] = s1v * acc[mi][ni][3] + (row + 8 == col + 1 ? s0v : 0.f);
        }
    }
    __syncwarp();
    int r = lane;
    float lsum = 0.f;
    for (int jc = 0; jc < 32; jc++) {
        float svv = 0.f;
        if (r >= jc) {
            svv = buf.H[r][jc];
            for (int p = 0; p < jc; p++) svv -= buf.H[r][p] * buf.H[jc][p];
        }
        float dj = __shfl_sync(0xffffffffu, svv, jc);
        dj = sqrtf(dj);
        if (r == jc) { buf.H[r][jc] = dj; lsum = logf(dj); }
        else if (r > jc) buf.H[r][jc] = svv / dj;
        __syncwarp();
    }
#pragma unroll
    for (int off = 16; off; off >>= 1)
        lsum += __shfl_xor_sync(0xffffffffu, lsum, off);
    if (r == 0) out[B * DIM + s] = 2.f * lsum;
}

// ------------------------- launch -------------------------
extern "C" void kernel_launch(void* const* d_in, const int* in_sizes, int n_in,
                              void* d_out, int out_size) {
    const float* x        = (const float*)d_in[0];
    const float* c        = (const float*)d_in[1];
    const float* w0       = (const float*)d_in[2];
    const float* w1       = (const float*)d_in[3];
    const float* Wz0_w    = (const float*)d_in[4];
    const float* Wz0_b    = (const float*)d_in[5];
    const float* Wc0_w    = (const float*)d_in[6];
    const float* Wc0_b    = (const float*)d_in[7];
    const float* an0_b    = (const float*)d_in[8];
    const float* an0_logs = (const float*)d_in[9];
    const float* Wz1_w    = (const float*)d_in[10];
    const float* Wz1_b    = (const float*)d_in[11];
    const float* Wx1_w    = (const float*)d_in[12];
    const float* Wx1_b    = (const float*)d_in[13];
    const float* Wc1_w    = (const float*)d_in[14];
    const float* Wc1_b    = (const float*)d_in[15];
    const float* an1_b    = (const float*)d_in[16];
    const float* an1_logs = (const float*)d_in[17];
    const float* Wz2_w    = (const float*)d_in[18];
    const float* Wz2_b    = (const float*)d_in[19];
    const float* Wx2_w    = (const float*)d_in[20];
    const float* Wx2_b    = (const float*)d_in[21];
    const float* Wc2_w    = (const float*)d_in[22];
    const float* Wc2_b    = (const float*)d_in[23];
    const float* an2_b    = (const float*)d_in[24];
    const float* an2_logs = (const float*)d_in[25];
    const float* Wzout_w  = (const float*)d_in[26];
    const float* Wxout_w  = (const float*)d_in[27];
    float* out = (float*)d_out;

#define SYM(v, s) cudaGetSymbolAddress((void**)&v, s)
    float *swout, *Wx1t, *Wx2t;
    float *D0, *E0, *D1, *E1, *G2, *V2, *G1, *V1, *G0, *V0;
    bf16 *D0h, *D1h, *Wz0th, *M1t, *M2t;
    bf16 *SW1hi, *SW1lo, *SW2hi, *SW2lo, *SW1thi, *SW1tlo, *SW2thi, *SW2tlo;
    bf16 *Wc0hi, *Wc0lo, *Wc1hi, *Wc1lo, *Wc2hi, *Wc2lo;
    bf16 *Wz0hi, *Wz0lo, *Wx1hi, *Wx1lo, *Wx2hi, *Wx2lo;
    bf16 *xhi, *xlo, *chi, *clo;
    bf16 *z0hi, *z0lo, *z1hi, *z1lo, *G2hi, *G2lo, *G1hi, *G1lo;
    SYM(swout, g_swout); SYM(Wx1t, g_Wx1t); SYM(Wx2t, g_Wx2t);
    SYM(D0, g_D0); SYM(E0, g_E0); SYM(D1, g_D1); SYM(E1, g_E1);
    SYM(D0h, g_D0h); SYM(D1h, g_D1h);
    SYM(G2, g_G2); SYM(V2, g_V2); SYM(G1, g_G1); SYM(V1, g_V1);
    SYM(G0, g_G0); SYM(V0, g_V0);
    SYM(Wz0th, g_Wz0t_h); SYM(M1t, g_M1t); SYM(M2t, g_M2t);
    SYM(SW1hi, g_SW1hi); SYM(SW1lo, g_SW1lo); SYM(SW2hi, g_SW2hi); SYM(SW2lo, g_SW2lo);
    SYM(SW1thi, g_SW1thi); SYM(SW1tlo, g_SW1tlo); SYM(SW2thi, g_SW2thi); SYM(SW2tlo, g_SW2tlo);
    SYM(Wc0hi, g_Wc0hi); SYM(Wc0lo, g_Wc0lo); SYM(Wc1hi, g_Wc1hi); SYM(Wc1lo, g_Wc1lo);
    SYM(Wc2hi, g_Wc2hi); SYM(Wc2lo, g_Wc2lo);
    SYM(Wz0hi, g_Wz0hi); SYM(Wz0lo, g_Wz0lo); SYM(Wx1hi, g_Wx1hi); SYM(Wx1lo, g_Wx1lo);
    SYM(Wx2hi, g_Wx2hi); SYM(Wx2lo, g_Wx2lo);
    SYM(xhi, g_xhi); SYM(xlo, g_xlo); SYM(chi, g_chi); SYM(clo, g_clo);
    SYM(z0hi, g_z0hi); SYM(z0lo, g_z0lo); SYM(z1hi, g_z1hi); SYM(z1lo, g_z1lo);
    SYM(G2hi, g_G2hi); SYM(G2lo, g_G2lo); SYM(G1hi, g_G1hi); SYM(G1lo, g_G1lo);
#undef SYM

    k_prep<<<1024, 256>>>(Wz1_w, Wz2_w, Wzout_w, Wz0_w, Wx1_w, Wx2_w);
    k_tr<<<dim3(32, 32, 4), dim3(32, 8)>>>();
    k_split<<<1024, 256>>>(c, x, Wc0_w, Wc1_w, Wc2_w);

    dim3 gt(DIMH / 128, B / 64);
    k_fwd_tc<<<gt, 256>>>(chi, clo, Wc0hi, Wc0lo, DIMC,
                          xhi, xlo, Wz0hi, Wz0lo, DIM,
                          nullptr, nullptr, nullptr, nullptr, 0,
                          Wc0_b, Wz0_b, nullptr, an0_b, an0_logs, nullptr,
                          z0hi, z0lo, D0, E0, D0h, nullptr, nullptr, nullptr, nullptr);
    k_fwd_tc<<<gt, 256>>>(z0hi, z0lo, SW1hi, SW1lo, DIMH,
                          chi, clo, Wc1hi, Wc1lo, DIMC,
                          xhi, xlo, Wx1hi, Wx1lo, DIM,
                          Wz1_b, Wc1_b, Wx1_b, an1_b, an1_logs, nullptr,
                          z1hi, z1lo, D1, E1, D1h, nullptr, nullptr, nullptr, nullptr);
    k_fwd_tc<<<gt, 256>>>(z1hi, z1lo, SW2hi, SW2lo, DIMH,
                          chi, clo, Wc2hi, Wc2lo, DIMC,
                          xhi, xlo, Wx2hi, Wx2lo, DIM,
                          Wz2_b, Wc2_b, Wx2_b, an2_b, an2_logs, swout,
                          nullptr, nullptr, nullptr, nullptr, nullptr, G2, G2hi, G2lo, V2);

    k_u_tc<<<gt, 256>>>(G2hi, G2lo, SW2thi, SW2tlo, D1, E1, G1, G1hi, G1lo, V1);
    k_u_tc<<<gt, 256>>>(G1hi, G1lo, SW1thi, SW1tlo, D0, E0, G0, nullptr, nullptr, V0);

    k_f<<<B / 64, 256>>>(x, Wz0_w, Wx1_w, Wx2_w, Wxout_w, w0, w1, out);

    dim3 gm(DIMH / 128, B / 4);
    k_M_tc<<<gm, 256>>>(SW1hi, Wz0th, 0,          D0, Wx1t, M1t);
    k_M_tc<<<gm, 256>>>(SW2hi, M1t,   DIM * DIMH, D1, Wx2t, M2t);

    k_hess_tc<<<B / 8, 256>>>(Wz0th, w0, w1, out);
}